// round 15
// baseline (speedup 1.0000x reference)
#include <cuda_runtime.h>
#include <cuda_fp16.h>

#define NN 100000
#define NN_PAD 102400
#define EE 1600000
#define FIN 100
#define XS_W 104          // fp16 row width (13 x 8 halves, 16B chunks)
#define HID 128
#define NC 47
#define NC_PAD 48

// fp16 GEMM tiling: half2-pair smem tables [k2][*]
#define RSA2 72           // A stride: conflict-free frag loads
#define RSB2_1 136        // B stride gemm1
#define RSB2_2 56         // B stride gemm2
#define W1H_N (56 * 128)  // g_w1h elements (k2 0..55 x 128 cols)
#define W2H_N (64 * 48)   // g_w2h elements (k2 0..63 x 48 cols)

__device__ int      g_degi[NN_PAD];
__device__ int      g_rowstart[NN];
__device__ int      g_cursor[NN];        // scatter cursors (copy of rowstart)
__device__ int      g_csr[EE];
__device__ float    g_dinv[NN];
__device__ __half   g_xs[NN * XS_W];     // fp16( dinv[s] * x[s] )
__device__ float    g_aggx[NN * FIN];    // fp32 aggregated features
__device__ __half   g_h[NN * HID];       // fp16 relu((A~X)W1 + b1)
__device__ __half   g_hws[NN * NC_PAD];  // fp16( dinv[r] * (h@W2)[r] )
__device__ unsigned g_w1h[W1H_N];        // W1 as half2 pairs [k2][n]
__device__ unsigned g_w2h[W2H_N];        // W2 as half2 pairs [k2][n]

__device__ __forceinline__ void mma_f16(float c[4], unsigned a0, unsigned a1,
                                        unsigned a2, unsigned a3,
                                        unsigned b0, unsigned b1) {
    asm volatile(
        "mma.sync.aligned.m16n8k16.row.col.f32.f16.f16.f32 "
        "{%0,%1,%2,%3}, {%4,%5,%6,%7}, {%8,%9}, {%0,%1,%2,%3};"
        : "+f"(c[0]), "+f"(c[1]), "+f"(c[2]), "+f"(c[3])
        : "r"(a0), "r"(a1), "r"(a2), "r"(a3), "r"(b0), "r"(b1));
}

// exact fp32 convert-add of one uint4 of halves
__device__ __forceinline__ void acc8_add(float acc[8], uint4 v) {
    __half2* h = (__half2*)&v;
    float2 f0 = __half22float2(h[0]);
    float2 f1 = __half22float2(h[1]);
    float2 f2 = __half22float2(h[2]);
    float2 f3 = __half22float2(h[3]);
    acc[0] += f0.x; acc[1] += f0.y;
    acc[2] += f1.x; acc[3] += f1.y;
    acc[4] += f2.x; acc[5] += f2.y;
    acc[6] += f3.x; acc[7] += f3.y;
}

// fp16 tree-reduce 4 rows, one convert, fp32 accumulate
__device__ __forceinline__ void acc8_add4(float acc[8], uint4 a, uint4 b, uint4 c, uint4 d) {
    __half2* ha = (__half2*)&a;
    __half2* hb = (__half2*)&b;
    __half2* hc = (__half2*)&c;
    __half2* hd = (__half2*)&d;
#pragma unroll
    for (int k = 0; k < 4; k++) {
        __half2 s = __hadd2(__hadd2(ha[k], hb[k]), __hadd2(hc[k], hd[k]));
        float2 f = __half22float2(s);
        acc[2 * k] += f.x;
        acc[2 * k + 1] += f.y;
    }
}

// ---------------- CSR build ----------------
// degree count + fused weight fp16 conversion (no dependencies on graph)
__global__ void k_deg(const int* __restrict__ ei, const float* __restrict__ W1,
                      const float* __restrict__ W2) {
    int e = blockIdx.x * blockDim.x + threadIdx.x;
    if (e < EE) atomicAdd(&g_degi[ei[EE + e]], 1);
    if (e < W1H_N) {
        int k2 = e >> 7, n = e & 127;
        int kg = k2 * 2;
        float f0 = (kg < FIN) ? W1[kg * HID + n] : 0.f;
        float f1 = (kg + 1 < FIN) ? W1[(kg + 1) * HID + n] : 0.f;
        __half2 hh = __floats2half2_rn(f0, f1);
        g_w1h[e] = *(unsigned*)&hh;
    } else if (e < W1H_N + W2H_N) {
        int idx = e - W1H_N;
        int k2 = idx / 48, n = idx - k2 * 48;
        int kg = k2 * 2;
        float f0 = (n < NC) ? W2[kg * NC + n] : 0.f;
        float f1 = (n < NC) ? W2[(kg + 1) * NC + n] : 0.f;
        __half2 hh = __floats2half2_rn(f0, f1);
        g_w2h[idx] = *(unsigned*)&hh;
    }
}

__global__ void k_scan() {
    __shared__ int sh_w[32];
    __shared__ int sh_tot;
    int tid = threadIdx.x;
    int lane = tid & 31, wid = tid >> 5;
    int carry = 0;
    for (int base = 0; base < NN_PAD; base += 4096) {
        int i0 = base + tid * 4;
        int4 d = ((const int4*)g_degi)[i0 >> 2];
        int s0 = d.x, s1 = s0 + d.y, s2 = s1 + d.z, s3 = s2 + d.w;
        int tsum = s3;
        int v = tsum;
        #pragma unroll
        for (int off = 1; off < 32; off <<= 1) {
            int t = __shfl_up_sync(0xffffffffu, v, off);
            if (lane >= off) v += t;
        }
        int wexcl = v - tsum;
        if (lane == 31) sh_w[wid] = v;
        __syncthreads();
        if (wid == 0) {
            int wv = sh_w[lane];
            int u = wv;
            #pragma unroll
            for (int off = 1; off < 32; off <<= 1) {
                int t = __shfl_up_sync(0xffffffffu, u, off);
                if (lane >= off) u += t;
            }
            sh_w[lane] = u - wv;
            if (lane == 31) sh_tot = u;
        }
        __syncthreads();
        int off0 = carry + sh_w[wid] + wexcl;
        if (i0 + 0 < NN) { g_rowstart[i0 + 0] = off0;      g_cursor[i0 + 0] = off0;
                           g_dinv[i0 + 0] = rsqrtf((float)d.x + 1.f); }
        if (i0 + 1 < NN) { g_rowstart[i0 + 1] = off0 + s0; g_cursor[i0 + 1] = off0 + s0;
                           g_dinv[i0 + 1] = rsqrtf((float)d.y + 1.f); }
        if (i0 + 2 < NN) { g_rowstart[i0 + 2] = off0 + s1; g_cursor[i0 + 2] = off0 + s1;
                           g_dinv[i0 + 2] = rsqrtf((float)d.z + 1.f); }
        if (i0 + 3 < NN) { g_rowstart[i0 + 3] = off0 + s2; g_cursor[i0 + 3] = off0 + s2;
                           g_dinv[i0 + 3] = rsqrtf((float)d.w + 1.f); }
        carry += sh_tot;
        __syncthreads();
    }
}

// fill CSR (cursor-based, no eord) + build fp16 scaled feature table
__global__ void k_fill_conv(const int* __restrict__ ei, const float* __restrict__ x) {
    int t = blockIdx.x * blockDim.x + threadIdx.x;
    if (t < EE) {
        int pos = atomicAdd(&g_cursor[ei[EE + t]], 1);
        g_csr[pos] = ei[t];
    }
    if (t < NN * 13) {
        int n = t / 13, c = t - n * 13;
        float w = g_dinv[n];
        int base = c * 8;
        float f[8];
#pragma unroll
        for (int i = 0; i < 8; i++) {
            int col = base + i;
            float v = 0.f;
            if (col < FIN) v = x[n * FIN + col] * w;
            f[i] = v;
        }
        __half2 hh[4];
        hh[0] = __floats2half2_rn(f[0], f[1]);
        hh[1] = __floats2half2_rn(f[2], f[3]);
        hh[2] = __floats2half2_rn(f[4], f[5]);
        hh[3] = __floats2half2_rn(f[6], f[7]);
        ((uint4*)g_xs)[n * 13 + c] = *(uint4*)hh;
    }
}

// ---------------- layer 1 aggregation: TWO nodes per warp (R9-identical) ----------------
__global__ void __launch_bounds__(256) k_agg1() {
    int t = blockIdx.x * blockDim.x + threadIdx.x;
    int warp = t >> 5, lane = t & 31;
    int sub = lane >> 4;
    int l = lane & 15;
    int node = warp * 2 + sub;
    if (node >= NN) return;
    bool act = l < 13;
    const uint4* xs4 = (const uint4*)g_xs;
    float acc[8] = {0.f, 0.f, 0.f, 0.f, 0.f, 0.f, 0.f, 0.f};
    if (act) acc8_add(acc, xs4[node * 13 + l]);      // self loop (exact)
    int start = g_rowstart[node];
    int end = start + g_degi[node];
    int j = start;
    for (; j + 3 < end; j += 4) {
        int s0 = g_csr[j], s1 = g_csr[j + 1], s2 = g_csr[j + 2], s3 = g_csr[j + 3];
        if (act) {
            uint4 v0 = xs4[s0 * 13 + l];
            uint4 v1 = xs4[s1 * 13 + l];
            uint4 v2 = xs4[s2 * 13 + l];
            uint4 v3 = xs4[s3 * 13 + l];
            acc8_add4(acc, v0, v1, v2, v3);
        }
    }
    for (; j < end; j++) {
        int s0 = g_csr[j];
        if (act) acc8_add(acc, xs4[s0 * 13 + l]);
    }
    if (act) {
        float wd = g_dinv[node];
#pragma unroll
        for (int i = 0; i < 8; i++) acc[i] *= wd;
        int ob = node * FIN + l * 8;
        *(float4*)&g_aggx[ob] = make_float4(acc[0], acc[1], acc[2], acc[3]);
        if (l < 12)
            *(float4*)&g_aggx[ob + 4] = make_float4(acc[4], acc[5], acc[6], acc[7]);
    }
}

// ---------------- GEMM1 (fp16 mma, single-stage K, 256 thr): g_h = fp16(relu(aggx@W1+b1)) ----------------
// 8 warps: 2(M) x 4(N); tile 64(M) x 128(N)
__global__ void __launch_bounds__(256) k_gemm1(const float* __restrict__ b1) {
    __shared__ unsigned As2[56 * RSA2];      // 16.1 KB
    __shared__ unsigned Bs2[56 * RSB2_1];    // 29.8 KB
    int tid = threadIdx.x;
    int lane = tid & 31, wid = tid >> 5;
    int g = lane >> 2, q = lane & 3;
    int warp_m = wid & 1, warp_n = wid >> 1;  // 2 x 4
    int row0 = blockIdx.x * 64;
    float c[2][4][4];
#pragma unroll
    for (int mt = 0; mt < 2; mt++)
#pragma unroll
        for (int nt = 0; nt < 4; nt++)
#pragma unroll
            for (int r = 0; r < 4; r++) c[mt][nt][r] = 0.f;

    // stage A (fp32 -> half2 convert), whole K
    for (int i = tid; i < 56 * 64; i += 256) {
        int k2 = i >> 6, m = i & 63;
        int kg = k2 * 2;
        int gr = row0 + m;
        float f0 = 0.f, f1 = 0.f;
        if (gr < NN && kg < FIN) {
            f0 = g_aggx[gr * FIN + kg];
            if (kg + 1 < FIN) f1 = g_aggx[gr * FIN + kg + 1];
        }
        __half2 hh = __floats2half2_rn(f0, f1);
        As2[k2 * RSA2 + m] = *(unsigned*)&hh;
    }
    // stage B: raw copy of pre-converted weights
    for (int i = tid; i < W1H_N; i += 256) {
        int k2 = i >> 7, n = i & 127;
        Bs2[k2 * RSB2_1 + n] = g_w1h[i];
    }
    __syncthreads();

#pragma unroll
    for (int ch = 0; ch < 7; ch++) {
        int k2a = ch * 8 + q, k2b = ch * 8 + q + 4;
        unsigned a[2][4];
#pragma unroll
        for (int mt = 0; mt < 2; mt++) {
            int mi = warp_m * 32 + mt * 16 + g;
            a[mt][0] = As2[k2a * RSA2 + mi];
            a[mt][1] = As2[k2a * RSA2 + mi + 8];
            a[mt][2] = As2[k2b * RSA2 + mi];
            a[mt][3] = As2[k2b * RSA2 + mi + 8];
        }
#pragma unroll
        for (int nt = 0; nt < 4; nt++) {
            int ni = warp_n * 32 + nt * 8 + g;
            unsigned b0 = Bs2[k2a * RSB2_1 + ni];
            unsigned b1v = Bs2[k2b * RSB2_1 + ni];
#pragma unroll
            for (int mt = 0; mt < 2; mt++)
                mma_f16(c[mt][nt], a[mt][0], a[mt][1], a[mt][2], a[mt][3], b0, b1v);
        }
    }
    // epilogue: bias + relu -> fp16
#pragma unroll
    for (int mt = 0; mt < 2; mt++) {
        int row = row0 + warp_m * 32 + mt * 16 + g;
#pragma unroll
        for (int nt = 0; nt < 4; nt++) {
            int col = warp_n * 32 + nt * 8 + 2 * q;
            float bb0 = b1[col], bb1 = b1[col + 1];
            if (row < NN) {
                float v0 = c[mt][nt][0] + bb0, v1 = c[mt][nt][1] + bb1;
                __half2 o = __floats2half2_rn(v0 > 0.f ? v0 : 0.f, v1 > 0.f ? v1 : 0.f);
                *(__half2*)&g_h[row * HID + col] = o;
            }
            if (row + 8 < NN) {
                float v2 = c[mt][nt][2] + bb0, v3 = c[mt][nt][3] + bb1;
                __half2 o = __floats2half2_rn(v2 > 0.f ? v2 : 0.f, v3 > 0.f ? v3 : 0.f);
                *(__half2*)&g_h[(row + 8) * HID + col] = o;
            }
        }
    }
}

// ---------------- GEMM2 (fp16 mma, single-stage K, 256 thr): g_hws = fp16(dinv*(g_h@W2)) ----------------
// 8 warps: 4(M) x 2(N); tile 64(M) x 48(N)
__global__ void __launch_bounds__(256) k_gemm2() {
    __shared__ unsigned As2[64 * RSA2];      // 18.4 KB
    __shared__ unsigned Bs2[64 * RSB2_2];    // 14.3 KB
    int tid = threadIdx.x;
    int lane = tid & 31, wid = tid >> 5;
    int g = lane >> 2, q = lane & 3;
    int warp_m = wid & 3, warp_n = wid >> 2;  // 4 x 2
    int row0 = blockIdx.x * 64;
    const unsigned* h_u = (const unsigned*)g_h;   // 64 uints per row
    float c[3][4];
#pragma unroll
    for (int nt = 0; nt < 3; nt++)
#pragma unroll
        for (int r = 0; r < 4; r++) c[nt][r] = 0.f;

    for (int i = tid; i < 64 * 64; i += 256) {
        int k2 = i >> 6, m = i & 63;
        int gr = row0 + m;
        unsigned v = 0;
        if (gr < NN) v = h_u[gr * 64 + k2];
        As2[k2 * RSA2 + m] = v;
    }
    for (int i = tid; i < W2H_N; i += 256) {
        int k2 = i / 48, n = i - k2 * 48;
        Bs2[k2 * RSB2_2 + n] = g_w2h[i];
    }
    __syncthreads();

#pragma unroll
    for (int ch = 0; ch < 8; ch++) {
        int k2a = ch * 8 + q, k2b = ch * 8 + q + 4;
        int mi = warp_m * 16 + g;
        unsigned a0 = As2[k2a * RSA2 + mi];
        unsigned a1 = As2[k2a * RSA2 + mi + 8];
        unsigned a2 = As2[k2b * RSA2 + mi];
        unsigned a3 = As2[k2b * RSA2 + mi + 8];
#pragma unroll
        for (int nt = 0; nt < 3; nt++) {
            int ni = warp_n * 24 + nt * 8 + g;
            unsigned b0 = Bs2[k2a * RSB2_2 + ni];
            unsigned b1v = Bs2[k2b * RSB2_2 + ni];
            mma_f16(c[nt], a0, a1, a2, a3, b0, b1v);
        }
    }
    int row = row0 + warp_m * 16 + g;
    float wd0 = (row < NN) ? g_dinv[row] : 0.f;
    float wd1 = (row + 8 < NN) ? g_dinv[row + 8] : 0.f;
#pragma unroll
    for (int nt = 0; nt < 3; nt++) {
        int col = warp_n * 24 + nt * 8 + 2 * q;
        if (row < NN)
            *(__half2*)&g_hws[row * NC_PAD + col] =
                __floats2half2_rn(c[nt][0] * wd0, c[nt][1] * wd0);
        if (row + 8 < NN)
            *(__half2*)&g_hws[(row + 8) * NC_PAD + col] =
                __floats2half2_rn(c[nt][2] * wd1, c[nt][3] * wd1);
    }
}

// ---------------- layer 2 aggregation: 8 threads per node (R9-identical) ----------------
__global__ void k_agg2(const float* __restrict__ b2, float* __restrict__ out) {
    int t = blockIdx.x * blockDim.x + threadIdx.x;
    int node = t >> 3, sub = t & 7;
    if (node >= NN) return;
    bool act = sub < 6;
    const uint4* hw4 = (const uint4*)g_hws;
    float acc[8] = {0.f, 0.f, 0.f, 0.f, 0.f, 0.f, 0.f, 0.f};
    if (act) acc8_add(acc, hw4[node * 6 + sub]);
    int start = g_rowstart[node];
    int end = start + g_degi[node];
    int j = start;
    for (; j + 3 < end; j += 4) {
        int s0 = g_csr[j], s1 = g_csr[j + 1], s2 = g_csr[j + 2], s3 = g_csr[j + 3];
        if (act) {
            uint4 v0 = hw4[s0 * 6 + sub];
            uint4 v1 = hw4[s1 * 6 + sub];
            uint4 v2 = hw4[s2 * 6 + sub];
            uint4 v3 = hw4[s3 * 6 + sub];
            acc8_add4(acc, v0, v1, v2, v3);
        }
    }
    for (; j < end; j++) {
        int s0 = g_csr[j];
        if (act) acc8_add(acc, hw4[s0 * 6 + sub]);
    }
    if (act) {
        float wd = g_dinv[node];
        int cb = sub * 8;
#pragma unroll
        for (int i = 0; i < 8; i++) {
            int col = cb + i;
            if (col < NC) out[node * NC + col] = acc[i] * wd + b2[col];
        }
    }
}

extern "C" void kernel_launch(void* const* d_in, const int* in_sizes, int n_in,
                              void* d_out, int out_size) {
    const float* x  = (const float*)d_in[0];
    const int*   ei = (const int*)d_in[1];
    const float* W1 = (const float*)d_in[2];
    const float* b1 = (const float*)d_in[3];
    const float* W2 = (const float*)d_in[4];
    const float* b2 = (const float*)d_in[5];
    float* out = (float*)d_out;

    void* degi_ptr = nullptr;
    cudaGetSymbolAddress(&degi_ptr, g_degi);
    cudaMemsetAsync(degi_ptr, 0, NN_PAD * sizeof(int));

    k_deg<<<(EE + 255) / 256, 256>>>(ei, W1, W2);       // 0 (+W conversion)
    k_scan<<<1, 1024>>>();                              // 1
    k_fill_conv<<<(EE + 255) / 256, 256>>>(ei, x);      // 2 (cursor fill)
    k_agg1<<<(NN * 16 + 255) / 256, 256>>>();           // 3 (profiled; sentinel)
    k_gemm1<<<(NN + 63) / 64, 256>>>(b1);               // 4
    k_gemm2<<<(NN + 63) / 64, 256>>>();                 // 5
    k_agg2<<<(NN * 8 + 255) / 256, 256>>>(b2, out);     // 6
}

// round 16
// speedup vs baseline: 1.1223x; 1.1223x over previous
#include <cuda_runtime.h>
#include <cuda_fp16.h>

#define NN 100000
#define NN_PAD 102400
#define EE 1600000
#define FIN 100
#define XS_W 104          // fp16 row width (13 x 8 halves, 16B chunks)
#define HID 128
#define NC 47
#define NC_PAD 48

// fp16 GEMM tiling: half2-pair smem tables [k2][*]
#define RSA2 72           // A stride: conflict-free frag loads
#define RSB2_1 136        // B stride gemm1
#define RSB2_2 56         // B stride gemm2
#define W1H_N (56 * 128)  // g_w1h elements (k2 0..55 x 128 cols)
#define W2H_N (64 * 48)   // g_w2h elements (k2 0..63 x 48 cols)

__device__ int      g_degi[NN_PAD];
__device__ int      g_rowstart[NN];
__device__ int      g_eord[EE];
__device__ int      g_csr[EE];
__device__ float    g_dinv[NN];
__device__ __half   g_xs[NN * XS_W];     // fp16( dinv[s] * x[s] )
__device__ float    g_aggx[NN * FIN];    // fp32 aggregated features
__device__ __half   g_h[NN * HID];       // fp16 relu((A~X)W1 + b1)
__device__ __half   g_hws[NN * NC_PAD];  // fp16( dinv[r] * (h@W2)[r] )
__device__ unsigned g_w1h[W1H_N];        // W1 as half2 pairs [k2][n]
__device__ unsigned g_w2h[W2H_N];        // W2 as half2 pairs [k2][n]

__device__ __forceinline__ void mma_f16(float c[4], unsigned a0, unsigned a1,
                                        unsigned a2, unsigned a3,
                                        unsigned b0, unsigned b1) {
    asm volatile(
        "mma.sync.aligned.m16n8k16.row.col.f32.f16.f16.f32 "
        "{%0,%1,%2,%3}, {%4,%5,%6,%7}, {%8,%9}, {%0,%1,%2,%3};"
        : "+f"(c[0]), "+f"(c[1]), "+f"(c[2]), "+f"(c[3])
        : "r"(a0), "r"(a1), "r"(a2), "r"(a3), "r"(b0), "r"(b1));
}

// exact fp32 convert-add of one uint4 of halves
__device__ __forceinline__ void acc8_add(float acc[8], uint4 v) {
    __half2* h = (__half2*)&v;
    float2 f0 = __half22float2(h[0]);
    float2 f1 = __half22float2(h[1]);
    float2 f2 = __half22float2(h[2]);
    float2 f3 = __half22float2(h[3]);
    acc[0] += f0.x; acc[1] += f0.y;
    acc[2] += f1.x; acc[3] += f1.y;
    acc[4] += f2.x; acc[5] += f2.y;
    acc[6] += f3.x; acc[7] += f3.y;
}

// fp16 tree-reduce 4 rows, one convert, fp32 accumulate
__device__ __forceinline__ void acc8_add4(float acc[8], uint4 a, uint4 b, uint4 c, uint4 d) {
    __half2* ha = (__half2*)&a;
    __half2* hb = (__half2*)&b;
    __half2* hc = (__half2*)&c;
    __half2* hd = (__half2*)&d;
#pragma unroll
    for (int k = 0; k < 4; k++) {
        __half2 s = __hadd2(__hadd2(ha[k], hb[k]), __hadd2(hc[k], hd[k]));
        float2 f = __half22float2(s);
        acc[2 * k] += f.x;
        acc[2 * k + 1] += f.y;
    }
}

// ---------------- CSR build ----------------
// degree count + fused weight fp16 conversion (no dependencies on graph)
__global__ void k_deg(const int* __restrict__ ei, const float* __restrict__ W1,
                      const float* __restrict__ W2) {
    int e = blockIdx.x * blockDim.x + threadIdx.x;
    if (e < EE) g_eord[e] = atomicAdd(&g_degi[ei[EE + e]], 1);
    if (e < W1H_N) {
        int k2 = e >> 7, n = e & 127;
        int kg = k2 * 2;
        float f0 = (kg < FIN) ? W1[kg * HID + n] : 0.f;
        float f1 = (kg + 1 < FIN) ? W1[(kg + 1) * HID + n] : 0.f;
        __half2 hh = __floats2half2_rn(f0, f1);
        g_w1h[e] = *(unsigned*)&hh;
    } else if (e < W1H_N + W2H_N) {
        int idx = e - W1H_N;
        int k2 = idx / 48, n = idx - k2 * 48;
        int kg = k2 * 2;
        float f0 = (n < NC) ? W2[kg * NC + n] : 0.f;
        float f1 = (n < NC) ? W2[(kg + 1) * NC + n] : 0.f;
        __half2 hh = __floats2half2_rn(f0, f1);
        g_w2h[idx] = *(unsigned*)&hh;
    }
}

__global__ void k_scan() {
    __shared__ int sh_w[32];
    __shared__ int sh_tot;
    int tid = threadIdx.x;
    int lane = tid & 31, wid = tid >> 5;
    int carry = 0;
    for (int base = 0; base < NN_PAD; base += 4096) {
        int i0 = base + tid * 4;
        int4 d = ((const int4*)g_degi)[i0 >> 2];
        int s0 = d.x, s1 = s0 + d.y, s2 = s1 + d.z, s3 = s2 + d.w;
        int tsum = s3;
        int v = tsum;
        #pragma unroll
        for (int off = 1; off < 32; off <<= 1) {
            int t = __shfl_up_sync(0xffffffffu, v, off);
            if (lane >= off) v += t;
        }
        int wexcl = v - tsum;
        if (lane == 31) sh_w[wid] = v;
        __syncthreads();
        if (wid == 0) {
            int wv = sh_w[lane];
            int u = wv;
            #pragma unroll
            for (int off = 1; off < 32; off <<= 1) {
                int t = __shfl_up_sync(0xffffffffu, u, off);
                if (lane >= off) u += t;
            }
            sh_w[lane] = u - wv;
            if (lane == 31) sh_tot = u;
        }
        __syncthreads();
        int off0 = carry + sh_w[wid] + wexcl;
        if (i0 + 0 < NN) { g_rowstart[i0 + 0] = off0;      g_dinv[i0 + 0] = rsqrtf((float)d.x + 1.f); }
        if (i0 + 1 < NN) { g_rowstart[i0 + 1] = off0 + s0; g_dinv[i0 + 1] = rsqrtf((float)d.y + 1.f); }
        if (i0 + 2 < NN) { g_rowstart[i0 + 2] = off0 + s1; g_dinv[i0 + 2] = rsqrtf((float)d.z + 1.f); }
        if (i0 + 3 < NN) { g_rowstart[i0 + 3] = off0 + s2; g_dinv[i0 + 3] = rsqrtf((float)d.w + 1.f); }
        carry += sh_tot;
        __syncthreads();
    }
}

// fill CSR (eord-based, atomic-free) + build fp16 scaled feature table
__global__ void k_fill_conv(const int* __restrict__ ei, const float* __restrict__ x) {
    int t = blockIdx.x * blockDim.x + threadIdx.x;
    if (t < EE)
        g_csr[g_rowstart[ei[EE + t]] + g_eord[t]] = ei[t];
    if (t < NN * 13) {
        int n = t / 13, c = t - n * 13;
        float w = g_dinv[n];
        int base = c * 8;
        float f[8];
#pragma unroll
        for (int i = 0; i < 8; i++) {
            int col = base + i;
            float v = 0.f;
            if (col < FIN) v = x[n * FIN + col] * w;
            f[i] = v;
        }
        __half2 hh[4];
        hh[0] = __floats2half2_rn(f[0], f[1]);
        hh[1] = __floats2half2_rn(f[2], f[3]);
        hh[2] = __floats2half2_rn(f[4], f[5]);
        hh[3] = __floats2half2_rn(f[6], f[7]);
        ((uint4*)g_xs)[n * 13 + c] = *(uint4*)hh;
    }
}

// ---------------- layer 1 aggregation: TWO nodes per warp, pipelined index loads ----------------
__global__ void __launch_bounds__(256) k_agg1() {
    int t = blockIdx.x * blockDim.x + threadIdx.x;
    int warp = t >> 5, lane = t & 31;
    int sub = lane >> 4;
    int l = lane & 15;
    int node = warp * 2 + sub;
    if (node >= NN) return;
    bool act = l < 13;
    const uint4* xs4 = (const uint4*)g_xs;
    float acc[8] = {0.f, 0.f, 0.f, 0.f, 0.f, 0.f, 0.f, 0.f};
    if (act) acc8_add(acc, xs4[node * 13 + l]);      // self loop (exact)
    int start = g_rowstart[node];
    int end = start + g_degi[node];
    int j = start;
    int rem = end - start;
    if (rem >= 4) {
        // prime the pipeline
        int s0 = g_csr[j], s1 = g_csr[j + 1], s2 = g_csr[j + 2], s3 = g_csr[j + 3];
        while (rem >= 8) {
            int n0 = g_csr[j + 4], n1 = g_csr[j + 5], n2 = g_csr[j + 6], n3 = g_csr[j + 7];
            if (act) {
                uint4 v0 = xs4[s0 * 13 + l];
                uint4 v1 = xs4[s1 * 13 + l];
                uint4 v2 = xs4[s2 * 13 + l];
                uint4 v3 = xs4[s3 * 13 + l];
                acc8_add4(acc, v0, v1, v2, v3);
            }
            s0 = n0; s1 = n1; s2 = n2; s3 = n3;
            j += 4; rem -= 4;
        }
        if (act) {
            uint4 v0 = xs4[s0 * 13 + l];
            uint4 v1 = xs4[s1 * 13 + l];
            uint4 v2 = xs4[s2 * 13 + l];
            uint4 v3 = xs4[s3 * 13 + l];
            acc8_add4(acc, v0, v1, v2, v3);
        }
        j += 4; rem -= 4;
    }
    for (; rem > 0; rem--, j++) {
        int s0 = g_csr[j];
        if (act) acc8_add(acc, xs4[s0 * 13 + l]);
    }
    if (act) {
        float wd = g_dinv[node];
#pragma unroll
        for (int i = 0; i < 8; i++) acc[i] *= wd;
        int ob = node * FIN + l * 8;
        *(float4*)&g_aggx[ob] = make_float4(acc[0], acc[1], acc[2], acc[3]);
        if (l < 12)
            *(float4*)&g_aggx[ob + 4] = make_float4(acc[4], acc[5], acc[6], acc[7]);
    }
}

// ---------------- GEMM1 (fp16 mma, single-stage K, 128 thr — R12-proven) ----------------
__global__ void __launch_bounds__(128) k_gemm1(const float* __restrict__ b1) {
    __shared__ unsigned As2[56 * RSA2];      // 16.1 KB
    __shared__ unsigned Bs2[56 * RSB2_1];    // 29.8 KB
    int tid = threadIdx.x;
    int lane = tid & 31, wid = tid >> 5;
    int g = lane >> 2, q = lane & 3;
    int warp_m = wid & 1, warp_n = wid >> 1;
    int row0 = blockIdx.x * 64;
    float c[2][8][4];
#pragma unroll
    for (int mt = 0; mt < 2; mt++)
#pragma unroll
        for (int nt = 0; nt < 8; nt++)
#pragma unroll
            for (int r = 0; r < 4; r++) c[mt][nt][r] = 0.f;

    for (int i = tid; i < 56 * 64; i += 128) {
        int k2 = i >> 6, m = i & 63;
        int kg = k2 * 2;
        int gr = row0 + m;
        float f0 = 0.f, f1 = 0.f;
        if (gr < NN && kg < FIN) {
            f0 = g_aggx[gr * FIN + kg];
            if (kg + 1 < FIN) f1 = g_aggx[gr * FIN + kg + 1];
        }
        __half2 hh = __floats2half2_rn(f0, f1);
        As2[k2 * RSA2 + m] = *(unsigned*)&hh;
    }
    for (int i = tid; i < W1H_N; i += 128) {
        int k2 = i >> 7, n = i & 127;
        Bs2[k2 * RSB2_1 + n] = g_w1h[i];
    }
    __syncthreads();

#pragma unroll
    for (int ch = 0; ch < 7; ch++) {
        int k2a = ch * 8 + q, k2b = ch * 8 + q + 4;
        unsigned a[2][4];
#pragma unroll
        for (int mt = 0; mt < 2; mt++) {
            int mi = warp_m * 32 + mt * 16 + g;
            a[mt][0] = As2[k2a * RSA2 + mi];
            a[mt][1] = As2[k2a * RSA2 + mi + 8];
            a[mt][2] = As2[k2b * RSA2 + mi];
            a[mt][3] = As2[k2b * RSA2 + mi + 8];
        }
#pragma unroll
        for (int nt = 0; nt < 8; nt++) {
            int ni = warp_n * 64 + nt * 8 + g;
            unsigned b0 = Bs2[k2a * RSB2_1 + ni];
            unsigned b1v = Bs2[k2b * RSB2_1 + ni];
#pragma unroll
            for (int mt = 0; mt < 2; mt++)
                mma_f16(c[mt][nt], a[mt][0], a[mt][1], a[mt][2], a[mt][3], b0, b1v);
        }
    }
#pragma unroll
    for (int mt = 0; mt < 2; mt++) {
        int row = row0 + warp_m * 32 + mt * 16 + g;
#pragma unroll
        for (int nt = 0; nt < 8; nt++) {
            int col = warp_n * 64 + nt * 8 + 2 * q;
            float bb0 = b1[col], bb1 = b1[col + 1];
            if (row < NN) {
                float v0 = c[mt][nt][0] + bb0, v1 = c[mt][nt][1] + bb1;
                __half2 o = __floats2half2_rn(v0 > 0.f ? v0 : 0.f, v1 > 0.f ? v1 : 0.f);
                *(__half2*)&g_h[row * HID + col] = o;
            }
            if (row + 8 < NN) {
                float v2 = c[mt][nt][2] + bb0, v3 = c[mt][nt][3] + bb1;
                __half2 o = __floats2half2_rn(v2 > 0.f ? v2 : 0.f, v3 > 0.f ? v3 : 0.f);
                *(__half2*)&g_h[(row + 8) * HID + col] = o;
            }
        }
    }
}

// ---------------- GEMM2 (fp16 mma, single-stage K, 128 thr — R12-proven) ----------------
__global__ void __launch_bounds__(128) k_gemm2() {
    __shared__ unsigned As2[64 * RSA2];      // 18.4 KB
    __shared__ unsigned Bs2[64 * RSB2_2];    // 14.3 KB
    int tid = threadIdx.x;
    int lane = tid & 31, wid = tid >> 5;
    int g = lane >> 2, q = lane & 3;
    int row0 = blockIdx.x * 64;
    const unsigned* h_u = (const unsigned*)g_h;
    float c[6][4];
#pragma unroll
    for (int nt = 0; nt < 6; nt++)
#pragma unroll
        for (int r = 0; r < 4; r++) c[nt][r] = 0.f;

    for (int i = tid; i < 64 * 64; i += 128) {
        int k2 = i >> 6, m = i & 63;
        int gr = row0 + m;
        unsigned v = 0;
        if (gr < NN) v = h_u[gr * 64 + k2];
        As2[k2 * RSA2 + m] = v;
    }
    for (int i = tid; i < W2H_N; i += 128) {
        int k2 = i / 48, n = i - k2 * 48;
        Bs2[k2 * RSB2_2 + n] = g_w2h[i];
    }
    __syncthreads();

#pragma unroll
    for (int ch = 0; ch < 8; ch++) {
        int k2a = ch * 8 + q, k2b = ch * 8 + q + 4;
        int mi = wid * 16 + g;
        unsigned a0 = As2[k2a * RSA2 + mi];
        unsigned a1 = As2[k2a * RSA2 + mi + 8];
        unsigned a2 = As2[k2b * RSA2 + mi];
        unsigned a3 = As2[k2b * RSA2 + mi + 8];
#pragma unroll
        for (int nt = 0; nt < 6; nt++) {
            int ni = nt * 8 + g;
            unsigned b0 = Bs2[k2a * RSB2_2 + ni];
            unsigned b1v = Bs2[k2b * RSB2_2 + ni];
            mma_f16(c[nt], a0, a1, a2, a3, b0, b1v);
        }
    }
    int row = row0 + wid * 16 + g;
    float wd0 = (row < NN) ? g_dinv[row] : 0.f;
    float wd1 = (row + 8 < NN) ? g_dinv[row + 8] : 0.f;
#pragma unroll
    for (int nt = 0; nt < 6; nt++) {
        int col = nt * 8 + 2 * q;
        if (row < NN)
            *(__half2*)&g_hws[row * NC_PAD + col] =
                __floats2half2_rn(c[nt][0] * wd0, c[nt][1] * wd0);
        if (row + 8 < NN)
            *(__half2*)&g_hws[(row + 8) * NC_PAD + col] =
                __floats2half2_rn(c[nt][2] * wd1, c[nt][3] * wd1);
    }
}

// ---------------- layer 2 aggregation: 8 threads per node ----------------
__global__ void k_agg2(const float* __restrict__ b2, float* __restrict__ out) {
    int t = blockIdx.x * blockDim.x + threadIdx.x;
    int node = t >> 3, sub = t & 7;
    if (node >= NN) return;
    bool act = sub < 6;
    const uint4* hw4 = (const uint4*)g_hws;
    float acc[8] = {0.f, 0.f, 0.f, 0.f, 0.f, 0.f, 0.f, 0.f};
    if (act) acc8_add(acc, hw4[node * 6 + sub]);
    int start = g_rowstart[node];
    int end = start + g_degi[node];
    int j = start;
    for (; j + 3 < end; j += 4) {
        int s0 = g_csr[j], s1 = g_csr[j + 1], s2 = g_csr[j + 2], s3 = g_csr[j + 3];
        if (act) {
            uint4 v0 = hw4[s0 * 6 + sub];
            uint4 v1 = hw4[s1 * 6 + sub];
            uint4 v2 = hw4[s2 * 6 + sub];
            uint4 v3 = hw4[s3 * 6 + sub];
            acc8_add4(acc, v0, v1, v2, v3);
        }
    }
    for (; j < end; j++) {
        int s0 = g_csr[j];
        if (act) acc8_add(acc, hw4[s0 * 6 + sub]);
    }
    if (act) {
        float wd = g_dinv[node];
        int cb = sub * 8;
#pragma unroll
        for (int i = 0; i < 8; i++) {
            int col = cb + i;
            if (col < NC) out[node * NC + col] = acc[i] * wd + b2[col];
        }
    }
}

extern "C" void kernel_launch(void* const* d_in, const int* in_sizes, int n_in,
                              void* d_out, int out_size) {
    const float* x  = (const float*)d_in[0];
    const int*   ei = (const int*)d_in[1];
    const float* W1 = (const float*)d_in[2];
    const float* b1 = (const float*)d_in[3];
    const float* W2 = (const float*)d_in[4];
    const float* b2 = (const float*)d_in[5];
    float* out = (float*)d_out;

    void* degi_ptr = nullptr;
    cudaGetSymbolAddress(&degi_ptr, g_degi);
    cudaMemsetAsync(degi_ptr, 0, NN_PAD * sizeof(int));

    k_deg<<<(EE + 255) / 256, 256>>>(ei, W1, W2);       // 0 (+W conversion, eord)
    k_scan<<<1, 1024>>>();                              // 1
    k_fill_conv<<<(EE + 255) / 256, 256>>>(ei, x);      // 2 (eord fill, atomic-free)
    k_agg1<<<(NN * 16 + 255) / 256, 256>>>();           // 3 (profiled; pipelined)
    k_gemm1<<<(NN + 63) / 64, 128>>>(b1);               // 4
    k_gemm2<<<(NN + 63) / 64, 128>>>();                 // 5
    k_agg2<<<(NN * 8 + 255) / 256, 256>>>(b2, out);     // 6
}

// round 17
// speedup vs baseline: 1.2814x; 1.1418x over previous
#include <cuda_runtime.h>
#include <cuda_fp16.h>

#define NN 100000
#define NN_PAD 102400
#define EE 1600000
#define FIN 100
#define XS_W 104          // fp16 row width (13 x 8 halves, 16B chunks)
#define HID 128
#define NC 47
#define NC_PAD 48

// fp16 GEMM tiling: half2-pair smem tables [k2][*]
#define RSA2 72           // A / h stride: conflict-free frag loads
#define RSB2_1 136        // W1 stride
#define RSB2_2 56         // W2 stride
#define W1H_N (56 * 128)  // g_w1h elements (k2 0..55 x 128 cols)
#define W2H_N (64 * 48)   // g_w2h elements (k2 0..63 x 48 cols)

__device__ int      g_degi[NN_PAD];
__device__ int      g_rowstart[NN];
__device__ int      g_eord[EE];
__device__ int      g_csr[EE];
__device__ float    g_dinv[NN];
__device__ __half   g_xs[NN * XS_W];     // fp16( dinv[s] * x[s] )
__device__ float    g_aggx[NN * FIN];    // fp32 aggregated features
__device__ __half   g_hws[NN * NC_PAD];  // fp16( dinv[r] * (h@W2)[r] )
__device__ unsigned g_w1h[W1H_N];        // W1 as half2 pairs [k2][n]
__device__ unsigned g_w2h[W2H_N];        // W2 as half2 pairs [k2][n]

__device__ __forceinline__ void mma_f16(float c[4], unsigned a0, unsigned a1,
                                        unsigned a2, unsigned a3,
                                        unsigned b0, unsigned b1) {
    asm volatile(
        "mma.sync.aligned.m16n8k16.row.col.f32.f16.f16.f32 "
        "{%0,%1,%2,%3}, {%4,%5,%6,%7}, {%8,%9}, {%0,%1,%2,%3};"
        : "+f"(c[0]), "+f"(c[1]), "+f"(c[2]), "+f"(c[3])
        : "r"(a0), "r"(a1), "r"(a2), "r"(a3), "r"(b0), "r"(b1));
}

// exact fp32 convert-add of one uint4 of halves
__device__ __forceinline__ void acc8_add(float acc[8], uint4 v) {
    __half2* h = (__half2*)&v;
    float2 f0 = __half22float2(h[0]);
    float2 f1 = __half22float2(h[1]);
    float2 f2 = __half22float2(h[2]);
    float2 f3 = __half22float2(h[3]);
    acc[0] += f0.x; acc[1] += f0.y;
    acc[2] += f1.x; acc[3] += f1.y;
    acc[4] += f2.x; acc[5] += f2.y;
    acc[6] += f3.x; acc[7] += f3.y;
}

// fp16 tree-reduce 4 rows, one convert, fp32 accumulate
__device__ __forceinline__ void acc8_add4(float acc[8], uint4 a, uint4 b, uint4 c, uint4 d) {
    __half2* ha = (__half2*)&a;
    __half2* hb = (__half2*)&b;
    __half2* hc = (__half2*)&c;
    __half2* hd = (__half2*)&d;
#pragma unroll
    for (int k = 0; k < 4; k++) {
        __half2 s = __hadd2(__hadd2(ha[k], hb[k]), __hadd2(hc[k], hd[k]));
        float2 f = __half22float2(s);
        acc[2 * k] += f.x;
        acc[2 * k + 1] += f.y;
    }
}

// ---------------- CSR build ----------------
// degree count + fused weight fp16 conversion (no dependencies on graph)
__global__ void k_deg(const int* __restrict__ ei, const float* __restrict__ W1,
                      const float* __restrict__ W2) {
    int e = blockIdx.x * blockDim.x + threadIdx.x;
    if (e < EE) g_eord[e] = atomicAdd(&g_degi[ei[EE + e]], 1);
    if (e < W1H_N) {
        int k2 = e >> 7, n = e & 127;
        int kg = k2 * 2;
        float f0 = (kg < FIN) ? W1[kg * HID + n] : 0.f;
        float f1 = (kg + 1 < FIN) ? W1[(kg + 1) * HID + n] : 0.f;
        __half2 hh = __floats2half2_rn(f0, f1);
        g_w1h[e] = *(unsigned*)&hh;
    } else if (e < W1H_N + W2H_N) {
        int idx = e - W1H_N;
        int k2 = idx / 48, n = idx - k2 * 48;
        int kg = k2 * 2;
        float f0 = (n < NC) ? W2[kg * NC + n] : 0.f;
        float f1 = (n < NC) ? W2[(kg + 1) * NC + n] : 0.f;
        __half2 hh = __floats2half2_rn(f0, f1);
        g_w2h[idx] = *(unsigned*)&hh;
    }
}

__global__ void k_scan() {
    __shared__ int sh_w[32];
    __shared__ int sh_tot;
    int tid = threadIdx.x;
    int lane = tid & 31, wid = tid >> 5;
    int carry = 0;
    for (int base = 0; base < NN_PAD; base += 4096) {
        int i0 = base + tid * 4;
        int4 d = ((const int4*)g_degi)[i0 >> 2];
        int s0 = d.x, s1 = s0 + d.y, s2 = s1 + d.z, s3 = s2 + d.w;
        int tsum = s3;
        int v = tsum;
        #pragma unroll
        for (int off = 1; off < 32; off <<= 1) {
            int t = __shfl_up_sync(0xffffffffu, v, off);
            if (lane >= off) v += t;
        }
        int wexcl = v - tsum;
        if (lane == 31) sh_w[wid] = v;
        __syncthreads();
        if (wid == 0) {
            int wv = sh_w[lane];
            int u = wv;
            #pragma unroll
            for (int off = 1; off < 32; off <<= 1) {
                int t = __shfl_up_sync(0xffffffffu, u, off);
                if (lane >= off) u += t;
            }
            sh_w[lane] = u - wv;
            if (lane == 31) sh_tot = u;
        }
        __syncthreads();
        int off0 = carry + sh_w[wid] + wexcl;
        if (i0 + 0 < NN) { g_rowstart[i0 + 0] = off0;      g_dinv[i0 + 0] = rsqrtf((float)d.x + 1.f); }
        if (i0 + 1 < NN) { g_rowstart[i0 + 1] = off0 + s0; g_dinv[i0 + 1] = rsqrtf((float)d.y + 1.f); }
        if (i0 + 2 < NN) { g_rowstart[i0 + 2] = off0 + s1; g_dinv[i0 + 2] = rsqrtf((float)d.z + 1.f); }
        if (i0 + 3 < NN) { g_rowstart[i0 + 3] = off0 + s2; g_dinv[i0 + 3] = rsqrtf((float)d.w + 1.f); }
        carry += sh_tot;
        __syncthreads();
    }
}

// fill CSR (eord-based, atomic-free) + build fp16 scaled feature table
__global__ void k_fill_conv(const int* __restrict__ ei, const float* __restrict__ x) {
    int t = blockIdx.x * blockDim.x + threadIdx.x;
    if (t < EE)
        g_csr[g_rowstart[ei[EE + t]] + g_eord[t]] = ei[t];
    if (t < NN * 13) {
        int n = t / 13, c = t - n * 13;
        float w = g_dinv[n];
        int base = c * 8;
        float f[8];
#pragma unroll
        for (int i = 0; i < 8; i++) {
            int col = base + i;
            float v = 0.f;
            if (col < FIN) v = x[n * FIN + col] * w;
            f[i] = v;
        }
        __half2 hh[4];
        hh[0] = __floats2half2_rn(f[0], f[1]);
        hh[1] = __floats2half2_rn(f[2], f[3]);
        hh[2] = __floats2half2_rn(f[4], f[5]);
        hh[3] = __floats2half2_rn(f[6], f[7]);
        ((uint4*)g_xs)[n * 13 + c] = *(uint4*)hh;
    }
}

// ---------------- layer 1 aggregation: TWO nodes per warp, pipelined (R16) ----------------
__global__ void __launch_bounds__(256) k_agg1() {
    int t = blockIdx.x * blockDim.x + threadIdx.x;
    int warp = t >> 5, lane = t & 31;
    int sub = lane >> 4;
    int l = lane & 15;
    int node = warp * 2 + sub;
    if (node >= NN) return;
    bool act = l < 13;
    const uint4* xs4 = (const uint4*)g_xs;
    float acc[8] = {0.f, 0.f, 0.f, 0.f, 0.f, 0.f, 0.f, 0.f};
    if (act) acc8_add(acc, xs4[node * 13 + l]);      // self loop (exact)
    int start = g_rowstart[node];
    int end = start + g_degi[node];
    int j = start;
    int rem = end - start;
    if (rem >= 4) {
        int s0 = g_csr[j], s1 = g_csr[j + 1], s2 = g_csr[j + 2], s3 = g_csr[j + 3];
        while (rem >= 8) {
            int n0 = g_csr[j + 4], n1 = g_csr[j + 5], n2 = g_csr[j + 6], n3 = g_csr[j + 7];
            if (act) {
                uint4 v0 = xs4[s0 * 13 + l];
                uint4 v1 = xs4[s1 * 13 + l];
                uint4 v2 = xs4[s2 * 13 + l];
                uint4 v3 = xs4[s3 * 13 + l];
                acc8_add4(acc, v0, v1, v2, v3);
            }
            s0 = n0; s1 = n1; s2 = n2; s3 = n3;
            j += 4; rem -= 4;
        }
        if (act) {
            uint4 v0 = xs4[s0 * 13 + l];
            uint4 v1 = xs4[s1 * 13 + l];
            uint4 v2 = xs4[s2 * 13 + l];
            uint4 v3 = xs4[s3 * 13 + l];
            acc8_add4(acc, v0, v1, v2, v3);
        }
        j += 4; rem -= 4;
    }
    for (; rem > 0; rem--, j++) {
        int s0 = g_csr[j];
        if (act) acc8_add(acc, xs4[s0 * 13 + l]);
    }
    if (act) {
        float wd = g_dinv[node];
#pragma unroll
        for (int i = 0; i < 8; i++) acc[i] *= wd;
        int ob = node * FIN + l * 8;
        *(float4*)&g_aggx[ob] = make_float4(acc[0], acc[1], acc[2], acc[3]);
        if (l < 12)
            *(float4*)&g_aggx[ob + 4] = make_float4(acc[4], acc[5], acc[6], acc[7]);
    }
}

// ---------------- FUSED GEMM: g_hws = fp16( dinv * (relu(aggx@W1+b1) @ W2) ) ----------------
// block 128 thr, 64 rows; phase1 = 64x128 (2x2 warps), phase2 = 64x48 (4 warps in M).
// smem reuse: sA = phase1 A (56x72) -> phase2 W2 (64x56); sB = phase1 W1 (56x136) -> phase2 h (64x72).
__global__ void __launch_bounds__(128) k_gemmF(const float* __restrict__ b1) {
    __shared__ unsigned sA[56 * RSA2];       // 16.1 KB
    __shared__ unsigned sB[56 * RSB2_1];     // 30.5 KB
    int tid = threadIdx.x;
    int lane = tid & 31, wid = tid >> 5;
    int g = lane >> 2, q = lane & 3;
    int warp_m = wid & 1, warp_n = wid >> 1;
    int row0 = blockIdx.x * 64;

    // ---- phase 1 staging ----
    for (int i = tid; i < 56 * 64; i += 128) {
        int k2 = i >> 6, m = i & 63;
        int kg = k2 * 2;
        int gr = row0 + m;
        float f0 = 0.f, f1 = 0.f;
        if (gr < NN && kg < FIN) {
            f0 = g_aggx[gr * FIN + kg];
            if (kg + 1 < FIN) f1 = g_aggx[gr * FIN + kg + 1];
        }
        __half2 hh = __floats2half2_rn(f0, f1);
        sA[k2 * RSA2 + m] = *(unsigned*)&hh;
    }
    for (int i = tid; i < W1H_N; i += 128) {
        int k2 = i >> 7, n = i & 127;
        sB[k2 * RSB2_1 + n] = g_w1h[i];
    }
    __syncthreads();

    // ---- phase 1 mma: c1 = aggx @ W1 ----
    float c1[2][8][4];
#pragma unroll
    for (int mt = 0; mt < 2; mt++)
#pragma unroll
        for (int nt = 0; nt < 8; nt++)
#pragma unroll
            for (int r = 0; r < 4; r++) c1[mt][nt][r] = 0.f;
#pragma unroll
    for (int ch = 0; ch < 7; ch++) {
        int k2a = ch * 8 + q, k2b = ch * 8 + q + 4;
        unsigned a[2][4];
#pragma unroll
        for (int mt = 0; mt < 2; mt++) {
            int mi = warp_m * 32 + mt * 16 + g;
            a[mt][0] = sA[k2a * RSA2 + mi];
            a[mt][1] = sA[k2a * RSA2 + mi + 8];
            a[mt][2] = sA[k2b * RSA2 + mi];
            a[mt][3] = sA[k2b * RSA2 + mi + 8];
        }
#pragma unroll
        for (int nt = 0; nt < 8; nt++) {
            int ni = warp_n * 64 + nt * 8 + g;
            unsigned b0 = sB[k2a * RSB2_1 + ni];
            unsigned b1v = sB[k2b * RSB2_1 + ni];
#pragma unroll
            for (int mt = 0; mt < 2; mt++)
                mma_f16(c1[mt][nt], a[mt][0], a[mt][1], a[mt][2], a[mt][3], b0, b1v);
        }
    }
    __syncthreads();   // done reading sA/sB

    // ---- inter-phase: h -> sB [k2][m] stride 72; W2 -> sA [k2][n] stride 56 ----
    for (int i = tid; i < W2H_N; i += 128) {
        int k2 = i / 48, n = i - k2 * 48;
        sA[k2 * RSB2_2 + n] = g_w2h[i];
    }
#pragma unroll
    for (int mt = 0; mt < 2; mt++) {
        int m0 = warp_m * 32 + mt * 16 + g;
#pragma unroll
        for (int nt = 0; nt < 8; nt++) {
            int col = warp_n * 64 + nt * 8 + 2 * q;
            int k2 = col >> 1;                    // warp_n*32 + nt*4 + q
            float bb0 = b1[col], bb1 = b1[col + 1];
            float v0 = c1[mt][nt][0] + bb0, v1 = c1[mt][nt][1] + bb1;
            __half2 h0 = __floats2half2_rn(v0 > 0.f ? v0 : 0.f, v1 > 0.f ? v1 : 0.f);
            sB[k2 * RSA2 + m0] = *(unsigned*)&h0;
            float v2 = c1[mt][nt][2] + bb0, v3 = c1[mt][nt][3] + bb1;
            __half2 h1 = __floats2half2_rn(v2 > 0.f ? v2 : 0.f, v3 > 0.f ? v3 : 0.f);
            sB[k2 * RSA2 + m0 + 8] = *(unsigned*)&h1;
        }
    }
    __syncthreads();

    // ---- phase 2 mma: c2 = h @ W2 (warps stacked in M: wid*16) ----
    float c2[6][4];
#pragma unroll
    for (int nt = 0; nt < 6; nt++)
#pragma unroll
        for (int r = 0; r < 4; r++) c2[nt][r] = 0.f;
#pragma unroll
    for (int ch = 0; ch < 8; ch++) {
        int k2a = ch * 8 + q, k2b = ch * 8 + q + 4;
        int mi = wid * 16 + g;
        unsigned a0 = sB[k2a * RSA2 + mi];
        unsigned a1 = sB[k2a * RSA2 + mi + 8];
        unsigned a2 = sB[k2b * RSA2 + mi];
        unsigned a3 = sB[k2b * RSA2 + mi + 8];
#pragma unroll
        for (int nt = 0; nt < 6; nt++) {
            int ni = nt * 8 + g;
            unsigned b0 = sA[k2a * RSB2_2 + ni];
            unsigned b1v = sA[k2b * RSB2_2 + ni];
            mma_f16(c2[nt], a0, a1, a2, a3, b0, b1v);
        }
    }
    int row = row0 + wid * 16 + g;
    float wd0 = (row < NN) ? g_dinv[row] : 0.f;
    float wd1 = (row + 8 < NN) ? g_dinv[row + 8] : 0.f;
#pragma unroll
    for (int nt = 0; nt < 6; nt++) {
        int col = nt * 8 + 2 * q;
        if (row < NN)
            *(__half2*)&g_hws[row * NC_PAD + col] =
                __floats2half2_rn(c2[nt][0] * wd0, c2[nt][1] * wd0);
        if (row + 8 < NN)
            *(__half2*)&g_hws[(row + 8) * NC_PAD + col] =
                __floats2half2_rn(c2[nt][2] * wd1, c2[nt][3] * wd1);
    }
}

// ---------------- layer 2 aggregation: 8 threads per node ----------------
__global__ void k_agg2(const float* __restrict__ b2, float* __restrict__ out) {
    int t = blockIdx.x * blockDim.x + threadIdx.x;
    int node = t >> 3, sub = t & 7;
    if (node >= NN) return;
    bool act = sub < 6;
    const uint4* hw4 = (const uint4*)g_hws;
    float acc[8] = {0.f, 0.f, 0.f, 0.f, 0.f, 0.f, 0.f, 0.f};
    if (act) acc8_add(acc, hw4[node * 6 + sub]);
    int start = g_rowstart[node];
    int end = start + g_degi[node];
    int j = start;
    for (; j + 3 < end; j += 4) {
        int s0 = g_csr[j], s1 = g_csr[j + 1], s2 = g_csr[j + 2], s3 = g_csr[j + 3];
        if (act) {
            uint4 v0 = hw4[s0 * 6 + sub];
            uint4 v1 = hw4[s1 * 6 + sub];
            uint4 v2 = hw4[s2 * 6 + sub];
            uint4 v3 = hw4[s3 * 6 + sub];
            acc8_add4(acc, v0, v1, v2, v3);
        }
    }
    for (; j < end; j++) {
        int s0 = g_csr[j];
        if (act) acc8_add(acc, hw4[s0 * 6 + sub]);
    }
    if (act) {
        float wd = g_dinv[node];
        int cb = sub * 8;
#pragma unroll
        for (int i = 0; i < 8; i++) {
            int col = cb + i;
            if (col < NC) out[node * NC + col] = acc[i] * wd + b2[col];
        }
    }
}

extern "C" void kernel_launch(void* const* d_in, const int* in_sizes, int n_in,
                              void* d_out, int out_size) {
    const float* x  = (const float*)d_in[0];
    const int*   ei = (const int*)d_in[1];
    const float* W1 = (const float*)d_in[2];
    const float* b1 = (const float*)d_in[3];
    const float* W2 = (const float*)d_in[4];
    const float* b2 = (const float*)d_in[5];
    float* out = (float*)d_out;

    void* degi_ptr = nullptr;
    cudaGetSymbolAddress(&degi_ptr, g_degi);
    cudaMemsetAsync(degi_ptr, 0, NN_PAD * sizeof(int));

    k_deg<<<(EE + 255) / 256, 256>>>(ei, W1, W2);       // 0 (+W conversion, eord)
    k_scan<<<1, 1024>>>();                              // 1
    k_fill_conv<<<(EE + 255) / 256, 256>>>(ei, x);      // 2 (eord fill, atomic-free)
    k_agg1<<<(NN * 16 + 255) / 256, 256>>>();           // 3 (profiled; sentinel)
    k_gemmF<<<(NN + 63) / 64, 128>>>(b1);               // 4 (fused GEMM1+GEMM2)
    k_agg2<<<(NN * 8 + 255) / 256, 256>>>(b2, out);     // 5
}